// round 3
// baseline (speedup 1.0000x reference)
#include <cuda_runtime.h>

// Problem constants (fixed shapes for this problem).
#define N_ROWS 65536   // 16*64*64
#define D      256     // embedding dim
#define K      1024    // num codewords

#define ROWS_PER_CTA 128
#define KC           128    // codeword columns per chunk (8x8 microtile / thread)
#define KS           64     // k-dim slice held in smem for the dict chunk
#define XS_STRIDE    132    // padded row stride for transposed x tile

typedef unsigned long long ull;

// Scratch (no allocations allowed -> __device__ globals).
__device__ int    g_code_idx[N_ROWS];
__device__ float  g_dsq[K];
__device__ double g_loss;

// ---- packed f32x2 helpers (FFMA2 path: 2 fp32 FMAs per FMA-pipe slot) ----
__device__ __forceinline__ ull pk2(float lo, float hi) {
    ull r; asm("mov.b64 %0, {%1, %2};" : "=l"(r) : "f"(lo), "f"(hi)); return r;
}
__device__ __forceinline__ void upk2(float& lo, float& hi, ull v) {
    asm("mov.b64 {%0, %1}, %2;" : "=f"(lo), "=f"(hi) : "l"(v));
}
__device__ __forceinline__ ull fma2(ull a, ull b, ull c) {
    ull r; asm("fma.rn.f32x2 %0, %1, %2, %3;" : "=l"(r) : "l"(a), "l"(b), "l"(c));
    return r;
}

// ---------------------------------------------------------------------------
// Kernel 0: per-codeword squared norms (d ascending, matching reference
// accumulation order) + zero the loss accumulator (graph-safe determinism).
// ---------------------------------------------------------------------------
__global__ void prep_kernel(const float* __restrict__ dict) {
    int k = blockIdx.x * blockDim.x + threadIdx.x;
    if (k == 0) g_loss = 0.0;
    if (k < K) {
        float s = 0.f;
        for (int d = 0; d < D; ++d) {
            float v = dict[d * K + k];
            s = fmaf(v, v, s);
        }
        g_dsq[k] = s;
    }
}

// ---------------------------------------------------------------------------
// Kernel 1: fused distance GEMM + argmin.
// CTA: 128 rows of x. x tile lives transposed in smem for the whole kernel.
// K processed in 8 chunks of 128 codewords; within a chunk the k-dim is
// sliced (KS=64) through a 32KB smem dict buffer.
// 256 threads = 16x16; each thread owns an 8-row x 8-col microtile using
// packed fma.rn.f32x2 (32 FFMA2 / kk / thread).
// dist = (||f||^2 + ||d||^2) - 2*sim ; argmin first-index tie-breaking.
// ---------------------------------------------------------------------------
__global__ void __launch_bounds__(256, 1)
dist_argmin_kernel(const float* __restrict__ x, const float* __restrict__ dict) {
    extern __shared__ float smem[];
    float* xs  = smem;                     // [D][XS_STRIDE] : xs[k*132 + m]
    float* ds  = xs + D * XS_STRIDE;       // [KS][KC]       : ds[kl*128 + c]
    float* fsq = ds + KS * KC;             // [128]

    const int tid  = threadIdx.x;
    const int tx   = tid & 15;    // codeword-column group (8 cols each)
    const int ty   = tid >> 4;    // row group (8 rows each)
    const int row0 = blockIdx.x * ROWS_PER_CTA;

    // Load x tile transposed into smem (global float4 reads, coalesced).
    #pragma unroll 4
    for (int i = 0; i < (ROWS_PER_CTA * D) / (256 * 4); ++i) {
        int lin = i * 256 + tid;           // float4 index
        int m  = lin >> 6;                 // row within tile (64 float4 per row)
        int k4 = (lin & 63) * 4;
        float4 v = *(const float4*)(x + (size_t)(row0 + m) * D + k4);
        xs[(k4 + 0) * XS_STRIDE + m] = v.x;
        xs[(k4 + 1) * XS_STRIDE + m] = v.y;
        xs[(k4 + 2) * XS_STRIDE + m] = v.z;
        xs[(k4 + 3) * XS_STRIDE + m] = v.w;
    }
    __syncthreads();

    // ||f||^2 per row, d ascending. Bank (4k+m)%32: conflict-free across m.
    if (tid < ROWS_PER_CTA) {
        float s = 0.f;
        for (int k = 0; k < D; ++k) {
            float v = xs[k * XS_STRIDE + tid];
            s = fmaf(v, v, s);
        }
        fsq[tid] = s;
    }
    __syncthreads();

    float fs[8];
    #pragma unroll
    for (int i = 0; i < 8; ++i) fs[i] = fsq[ty * 8 + i];

    float best_v[8];
    int   best_i[8];
    #pragma unroll
    for (int i = 0; i < 8; ++i) { best_v[i] = 3.4e38f; best_i[i] = 0; }

    const float* xsp = xs + ty * 8;
    const float* dsp = ds + tx * 8;

    for (int c0 = 0; c0 < K; c0 += KC) {
        ull acc[8][4];
        #pragma unroll
        for (int i = 0; i < 8; ++i)
            #pragma unroll
            for (int j = 0; j < 4; ++j) acc[i][j] = 0ULL;

        for (int ks = 0; ks < D; ks += KS) {
            // Load dict slice [KS][KC] (coalesced LDG.128, conflict-free STS).
            #pragma unroll
            for (int i = 0; i < (KS * KC) / (256 * 4); ++i) {
                int lin = i * 256 + tid;   // float4 index (32 per row)
                int kl  = lin >> 5;
                int c4  = (lin & 31) * 4;
                *(float4*)(ds + kl * KC + c4) =
                    *(const float4*)(dict + (size_t)(ks + kl) * K + c0 + c4);
            }
            __syncthreads();

            #pragma unroll 2
            for (int kk = 0; kk < KS; ++kk) {
                float4 a0 = *(const float4*)(xsp + (ks + kk) * XS_STRIDE);
                float4 a1 = *(const float4*)(xsp + (ks + kk) * XS_STRIDE + 4);
                float4 b0 = *(const float4*)(dsp + kk * KC);
                float4 b1 = *(const float4*)(dsp + kk * KC + 4);
                ull bp[4] = { pk2(b0.x, b0.y), pk2(b0.z, b0.w),
                              pk2(b1.x, b1.y), pk2(b1.z, b1.w) };
                float av[8] = { a0.x, a0.y, a0.z, a0.w, a1.x, a1.y, a1.z, a1.w };
                #pragma unroll
                for (int i = 0; i < 8; ++i) {
                    ull ad = pk2(av[i], av[i]);
                    #pragma unroll
                    for (int j = 0; j < 4; ++j)
                        acc[i][j] = fma2(ad, bp[j], acc[i][j]);
                }
            }
            __syncthreads();
        }

        // Epilogue: distances + per-row argmin for this 128-col chunk.
        float dq[8];
        #pragma unroll
        for (int j = 0; j < 8; ++j) dq[j] = g_dsq[c0 + tx * 8 + j];

        #pragma unroll
        for (int i = 0; i < 8; ++i) {
            float s[8];
            #pragma unroll
            for (int j = 0; j < 4; ++j) upk2(s[2 * j], s[2 * j + 1], acc[i][j]);

            float bv_ = (fs[i] + dq[0]) - 2.f * s[0];
            int   bi_ = c0 + tx * 8;
            #pragma unroll
            for (int j = 1; j < 8; ++j) {
                float dv = (fs[i] + dq[j]) - 2.f * s[j];
                if (dv < bv_) { bv_ = dv; bi_ = c0 + tx * 8 + j; }
            }
            // Reduce across the 16 tx lanes (width-16), tie -> lower index.
            #pragma unroll
            for (int off = 8; off >= 1; off >>= 1) {
                float ov = __shfl_down_sync(0xFFFFFFFFu, bv_, off, 16);
                int   oi = __shfl_down_sync(0xFFFFFFFFu, bi_, off, 16);
                if (ov < bv_ || (ov == bv_ && oi < bi_)) { bv_ = ov; bi_ = oi; }
            }
            if (bv_ < best_v[i]) { best_v[i] = bv_; best_i[i] = bi_; }
        }
    }

    // tx==0 lane of each ty-group holds the final result for its 8 rows.
    if (tx == 0) {
        #pragma unroll
        for (int i = 0; i < 8; ++i)
            g_code_idx[row0 + ty * 8 + i] = best_i[i];
    }
}

// ---------------------------------------------------------------------------
// Kernel 2: gather quantized rows, write output (q_st == q numerically),
// accumulate sum((x-q)^2) -> g_loss (one double atomic per CTA).
// One warp per row; dict (1 MB) stays L2-resident.
// ---------------------------------------------------------------------------
__global__ void gather_loss_kernel(const float* __restrict__ x,
                                   const float* __restrict__ dict,
                                   float* __restrict__ out) {
    __shared__ double bsum[8];
    int warp = threadIdx.x >> 5;
    int lane = threadIdx.x & 31;
    int row  = blockIdx.x * 8 + warp;

    int idx = g_code_idx[row];   // uniform across lanes -> broadcast
    float local = 0.f;
    #pragma unroll
    for (int j = 0; j < 8; ++j) {
        int d = j * 32 + lane;
        float q  = 0.5f * dict[(size_t)d * K + idx];
        float xv = x[(size_t)row * D + d];
        out[(size_t)row * D + d] = q;
        float df = xv - q;
        local = fmaf(df, df, local);
    }
    #pragma unroll
    for (int off = 16; off; off >>= 1)
        local += __shfl_down_sync(0xFFFFFFFFu, local, off);
    if (lane == 0) bsum[warp] = (double)local;
    __syncthreads();
    if (threadIdx.x == 0) {
        double s = 0.0;
        #pragma unroll
        for (int w = 0; w < 8; ++w) s += bsum[w];
        atomicAdd(&g_loss, s);
    }
}

// ---------------------------------------------------------------------------
// Kernel 3: loss = (1 + 0.25) * mean((x - q)^2), appended after q.
// ---------------------------------------------------------------------------
__global__ void finalize_kernel(float* __restrict__ out, int write_loss) {
    if (write_loss && threadIdx.x == 0) {
        out[(size_t)N_ROWS * D] =
            (float)(1.25 * g_loss / (double)((size_t)N_ROWS * D));
    }
}

extern "C" void kernel_launch(void* const* d_in, const int* in_sizes, int n_in,
                              void* d_out, int out_size) {
    const float* x    = (const float*)d_in[0];   // [N_ROWS, D] fp32
    const float* dict = (const float*)d_in[1];   // [D, K] fp32
    float* out = (float*)d_out;

    size_t smem = (size_t)(D * XS_STRIDE + KS * KC + ROWS_PER_CTA)
                      * sizeof(float);            // ~169 KB
    cudaFuncSetAttribute(dist_argmin_kernel,
                         cudaFuncAttributeMaxDynamicSharedMemorySize, (int)smem);

    prep_kernel<<<(K + 255) / 256, 256>>>(dict);
    dist_argmin_kernel<<<N_ROWS / ROWS_PER_CTA, 256, smem>>>(x, dict);
    gather_loss_kernel<<<N_ROWS / 8, 256>>>(x, dict, out);
    finalize_kernel<<<1, 32>>>(out, out_size > N_ROWS * D ? 1 : 0);
}

// round 8
// speedup vs baseline: 1.5187x; 1.5187x over previous
#include <cuda_runtime.h>
#include <cuda_bf16.h>
#include <cstdint>

#define N_ROWS 65536   // 16*64*64
#define D      256     // embedding dim
#define K      1024    // num codewords
#define MARGIN 1.2e-2f // approx-vs-exact argmin safety margin (~8 sigma)

// ---------------- device scratch (no allocations allowed) ----------------
__device__ __nv_bfloat16 g_xh[(size_t)N_ROWS * D];   // 32MB  x hi
__device__ __nv_bfloat16 g_dh[(size_t)K * D];        // dict^T hi  [n][k]
__device__ __nv_bfloat16 g_dl[(size_t)K * D];        // dict^T lo  [n][k]
__device__ float  g_fs[N_ROWS];
__device__ float  g_dsq[K];
__device__ int    g_code_idx[N_ROWS];
__device__ int    g_flag_rows[N_ROWS];
__device__ int    g_flag_cnt;
__device__ double g_loss;

__device__ __forceinline__ uint32_t smem_u32(const void* p) {
    uint32_t a;
    asm("{ .reg .u64 t; cvta.to.shared.u64 t, %1; cvt.u32.u64 %0, t; }"
        : "=r"(a) : "l"(p));
    return a;
}
__device__ __forceinline__ void ldsm_x4(uint32_t* r, uint32_t addr) {
    asm volatile("ldmatrix.sync.aligned.m8n8.x4.shared.b16 {%0,%1,%2,%3}, [%4];"
                 : "=r"(r[0]), "=r"(r[1]), "=r"(r[2]), "=r"(r[3]) : "r"(addr));
}
__device__ __forceinline__ void mma_bf16(float* c, const uint32_t* a,
                                         const uint32_t* b) {
    asm volatile(
        "mma.sync.aligned.m16n8k16.row.col.f32.bf16.bf16.f32 "
        "{%0,%1,%2,%3}, {%4,%5,%6,%7}, {%8,%9}, {%0,%1,%2,%3};"
        : "+f"(c[0]), "+f"(c[1]), "+f"(c[2]), "+f"(c[3])
        : "r"(a[0]), "r"(a[1]), "r"(a[2]), "r"(a[3]), "r"(b[0]), "r"(b[1]));
}

// ---------------------------------------------------------------------------
// K0a: dict -> dsq (exact fp32, d ascending) + transposed bf16 hi/lo split.
// ---------------------------------------------------------------------------
__global__ void prep_dict_kernel(const float* __restrict__ dict) {
    int n = blockIdx.x * blockDim.x + threadIdx.x;
    if (blockIdx.x == 0 && threadIdx.x == 0) { g_loss = 0.0; g_flag_cnt = 0; }
    if (n < K) {
        float s = 0.f;
        for (int d = 0; d < D; ++d) {
            float v = dict[(size_t)d * K + n];
            s = fmaf(v, v, s);
            __nv_bfloat16 h = __float2bfloat16(v);
            g_dh[(size_t)n * D + d] = h;
            g_dl[(size_t)n * D + d] = __float2bfloat16(v - __bfloat162float(h));
        }
        g_dsq[n] = s;
    }
}

// ---------------------------------------------------------------------------
// K0b: x -> bf16 hi (coalesced) + exact fp32 ||f||^2 per row (k ascending).
// FIX (round 7 bug): loop must cover 128 rows x 64 float4 = 8192 float4
// across 256 threads -> 32 iterations, not 8.
// ---------------------------------------------------------------------------
#define XS_STRIDE 132
__global__ void __launch_bounds__(256, 1)
prep_x_kernel(const float* __restrict__ x) {
    extern __shared__ float xs[];    // [D][XS_STRIDE]
    const int tid  = threadIdx.x;
    const int row0 = blockIdx.x * 128;

    #pragma unroll 8
    for (int i = 0; i < 32; ++i) {         // <-- was 8: only rows 0..31 written
        int lin = i * 256 + tid;           // float4 index (0..8191)
        int m  = lin >> 6;                 // row in tile (64 float4 per row)
        int k4 = (lin & 63) * 4;
        float4 v = *(const float4*)(x + (size_t)(row0 + m) * D + k4);
        xs[(k4 + 0) * XS_STRIDE + m] = v.x;
        xs[(k4 + 1) * XS_STRIDE + m] = v.y;
        xs[(k4 + 2) * XS_STRIDE + m] = v.z;
        xs[(k4 + 3) * XS_STRIDE + m] = v.w;
        __nv_bfloat162 h01 = {__float2bfloat16(v.x), __float2bfloat16(v.y)};
        __nv_bfloat162 h23 = {__float2bfloat16(v.z), __float2bfloat16(v.w)};
        size_t base = (size_t)(row0 + m) * D + k4;
        *(__nv_bfloat162*)(g_xh + base)     = h01;
        *(__nv_bfloat162*)(g_xh + base + 2) = h23;
    }
    __syncthreads();
    if (tid < 128) {
        float s = 0.f;
        for (int k = 0; k < D; ++k) {
            float v = xs[k * XS_STRIDE + tid];
            s = fmaf(v, v, s);
        }
        g_fs[row0 + tid] = s;
    }
}

// ---------------------------------------------------------------------------
// K1: bf16 mma.sync distance GEMM + top-2 argmin with margin flagging.
// CTA = 128 rows; 16 chunks of 64 codewords; 8 warps as 4 rowgrp x 2 colgrp,
// warp tile 32x32 (2 m-tiles x 4 n-tiles of m16n8k16).
// sim = xh*dh + xh*dl (fp32 accum); dist = fs + dsq - 2*sim.
// Cross-colgroup merge via smem scratch (round-6 fix, kept).
// ---------------------------------------------------------------------------
#define SAB 528      // row stride in BYTES (264 bf16, conflict-free)
#define AH_OFF  0
#define BH_OFF  67584
#define BL_OFF  101376
#define DSQ_OFF 135168
#define SM_TOT  139264

__global__ void __launch_bounds__(256, 1)
mma_argmin_kernel() {
    extern __shared__ char smem[];
    const uint32_t sb = smem_u32(smem);
    const int tid  = threadIdx.x;
    const int lane = tid & 31;
    const int warp = tid >> 5;
    const int rg   = warp >> 1;      // row group  (0..3) -> 32 rows
    const int cg   = warp & 1;       // col group  (0..1) -> 32 of 64 chunk cols
    const int row0 = blockIdx.x * 128;

    // Load A (xh) [128][256] into padded smem; dsq into smem.
    #pragma unroll
    for (int i = 0; i < 16; ++i) {
        int lin = i * 256 + tid;     // uint4 index
        int r  = lin >> 5;
        int k0 = (lin & 31) * 8;
        *(uint4*)(smem + AH_OFF + r * SAB + k0 * 2) =
            *(const uint4*)(g_xh + (size_t)(row0 + r) * D + k0);
    }
    ((float4*)(smem + DSQ_OFF))[tid] = ((const float4*)g_dsq)[tid];

    const int li  = lane & 7;
    const int gq  = lane >> 2;       // row within 8-row tile
    const int qq  = lane & 3;

    float fsr[4];
    #pragma unroll
    for (int rr = 0; rr < 4; ++rr)
        fsr[rr] = g_fs[row0 + rg * 32 + (rr >> 1) * 16 + (rr & 1) * 8 + gq];

    float m1[4], m2[4]; int i1[4];
    #pragma unroll
    for (int rr = 0; rr < 4; ++rr) { m1[rr] = 3.4e38f; m2[rr] = 3.4e38f; i1[rr] = 0; }

    const float* dsq_s = (const float*)(smem + DSQ_OFF);

    for (int c = 0; c < 16; ++c) {
        __syncthreads();   // previous chunk's reads done before overwrite
        #pragma unroll
        for (int i = 0; i < 8; ++i) {
            int lin = i * 256 + tid;   // uint4 index
            int n   = lin >> 5;
            int k0  = (lin & 31) * 8;
            size_t src = (size_t)(c * 64 + n) * D + k0;
            *(uint4*)(smem + BH_OFF + n * SAB + k0 * 2) = *(const uint4*)(g_dh + src);
            *(uint4*)(smem + BL_OFF + n * SAB + k0 * 2) = *(const uint4*)(g_dl + src);
        }
        __syncthreads();

        float acc[8][4];
        #pragma unroll
        for (int t = 0; t < 8; ++t)
            #pragma unroll
            for (int j = 0; j < 4; ++j) acc[t][j] = 0.f;

        #pragma unroll 4
        for (int ks = 0; ks < 16; ++ks) {
            const int k0 = ks * 16;
            uint32_t ah[2][4];
            #pragma unroll
            for (int rt = 0; rt < 2; ++rt) {
                int arow = rg * 32 + rt * 16 + li + ((lane >> 3) & 1) * 8;
                int acol = k0 + (lane >> 4) * 8;
                ldsm_x4(ah[rt], sb + AH_OFF + arow * SAB + acol * 2);
            }
            uint32_t bh[8], bl[8];
            #pragma unroll
            for (int hf = 0; hf < 2; ++hf) {
                int brow = cg * 32 + hf * 16 + li + (lane >> 4) * 8;
                int bcol = k0 + ((lane >> 3) & 1) * 8;
                ldsm_x4(bh + hf * 4, sb + BH_OFF + brow * SAB + bcol * 2);
                ldsm_x4(bl + hf * 4, sb + BL_OFF + brow * SAB + bcol * 2);
            }
            #pragma unroll
            for (int rt = 0; rt < 2; ++rt)
                #pragma unroll
                for (int nt = 0; nt < 4; ++nt) {
                    mma_bf16(acc[rt * 4 + nt], ah[rt], bh + nt * 2);
                    mma_bf16(acc[rt * 4 + nt], ah[rt], bl + nt * 2);
                }
        }

        // Epilogue: dist + top-2 per row over this warp's 32 columns.
        #pragma unroll
        for (int rt = 0; rt < 2; ++rt)
            #pragma unroll
            for (int nt = 0; nt < 4; ++nt) {
                const float* a = acc[rt * 4 + nt];
                int col0 = c * 64 + cg * 32 + nt * 8 + qq * 2;
                float ds0 = dsq_s[col0], ds1 = dsq_s[col0 + 1];
                #pragma unroll
                for (int h = 0; h < 2; ++h) {
                    int rr = rt * 2 + h;
                    float d0 = (fsr[rr] + ds0) - 2.f * a[h * 2 + 0];
                    float d1 = (fsr[rr] + ds1) - 2.f * a[h * 2 + 1];
                    if (d0 < m1[rr]) { m2[rr] = m1[rr]; m1[rr] = d0; i1[rr] = col0; }
                    else if (d0 < m2[rr]) m2[rr] = d0;
                    if (d1 < m1[rr]) { m2[rr] = m1[rr]; m1[rr] = d1; i1[rr] = col0 + 1; }
                    else if (d1 < m2[rr]) m2[rr] = d1;
                }
            }
    }

    // Merge top-2 across the 4 quad lanes (same gq).
    #pragma unroll
    for (int rr = 0; rr < 4; ++rr) {
        #pragma unroll
        for (int off = 1; off <= 2; off <<= 1) {
            float om1 = __shfl_xor_sync(0xFFFFFFFFu, m1[rr], off);
            float om2 = __shfl_xor_sync(0xFFFFFFFFu, m2[rr], off);
            int   oi1 = __shfl_xor_sync(0xFFFFFFFFu, i1[rr], off);
            if (om1 < m1[rr] || (om1 == m1[rr] && oi1 < i1[rr])) {
                m2[rr] = fminf(m1[rr], om2);
                m1[rr] = om1; i1[rr] = oi1;
            } else {
                m2[rr] = fminf(m2[rr], om1);
            }
        }
    }

    // Cross-colgroup merge: cg=1 spills to smem, cg=0 merges + writes.
    __syncthreads();                       // all B-buffer reads finished
    float* sm1 = (float*)(smem + BH_OFF);  // [128]
    float* sm2 = sm1 + 128;                // [128]
    int*   si1 = (int*)(sm2 + 128);        // [128]
    if (cg == 1 && qq == 0) {
        #pragma unroll
        for (int rr = 0; rr < 4; ++rr) {
            int rl = rg * 32 + (rr >> 1) * 16 + (rr & 1) * 8 + gq;
            sm1[rl] = m1[rr]; sm2[rl] = m2[rr]; si1[rl] = i1[rr];
        }
    }
    __syncthreads();
    if (cg == 0 && qq == 0) {
        #pragma unroll
        for (int rr = 0; rr < 4; ++rr) {
            int rl = rg * 32 + (rr >> 1) * 16 + (rr & 1) * 8 + gq;
            float om1 = sm1[rl], om2 = sm2[rl];
            int   oi1 = si1[rl];
            float f1, f2; int fi;
            if (om1 < m1[rr] || (om1 == m1[rr] && oi1 < i1[rr])) {
                f1 = om1; fi = oi1; f2 = fminf(m1[rr], om2);
            } else {
                f1 = m1[rr]; fi = i1[rr]; f2 = fminf(m2[rr], om1);
            }
            int row = row0 + rl;
            g_code_idx[row] = fi;
            if (f2 - f1 < MARGIN) {
                int e = atomicAdd(&g_flag_cnt, 1);
                g_flag_rows[e] = row;
            }
        }
    }
}

// ---------------------------------------------------------------------------
// K2: exact fp32 re-argmin for flagged rows, 8 rows per CTA.
// Tie -> lower index via packed u64 atomicMin (dist > 0, bits monotone).
// ---------------------------------------------------------------------------
__global__ void __launch_bounds__(256)
fallback_kernel(const float* __restrict__ x, const float* __restrict__ dict) {
    int bs = blockIdx.x * 8;
    int cnt = g_flag_cnt;
    if (bs >= cnt) return;
    int nr = min(8, cnt - bs);

    __shared__ float xs[8][260];
    __shared__ unsigned long long best[8];
    __shared__ float fsr[8];
    __shared__ int rows[8];

    int tid = threadIdx.x;
    if (tid < 8) {
        rows[tid] = g_flag_rows[bs + ((tid < nr) ? tid : 0)];
        best[tid] = ~0ULL;
        fsr[tid]  = g_fs[rows[tid]];
    }
    __syncthreads();
    #pragma unroll
    for (int r = 0; r < 8; ++r)
        xs[r][tid] = x[(size_t)rows[r] * D + tid];
    __syncthreads();

    #pragma unroll 1
    for (int j = 0; j < 4; ++j) {
        int c = j * 256 + tid;
        float acc[8];
        #pragma unroll
        for (int r = 0; r < 8; ++r) acc[r] = 0.f;
        for (int k = 0; k < D; k += 4) {
            float w0 = dict[(size_t)(k + 0) * K + c];
            float w1 = dict[(size_t)(k + 1) * K + c];
            float w2 = dict[(size_t)(k + 2) * K + c];
            float w3 = dict[(size_t)(k + 3) * K + c];
            #pragma unroll
            for (int r = 0; r < 8; ++r) {
                float4 xv = *(const float4*)&xs[r][k];
                float a = acc[r];
                a = fmaf(xv.x, w0, a);
                a = fmaf(xv.y, w1, a);
                a = fmaf(xv.z, w2, a);
                a = fmaf(xv.w, w3, a);
                acc[r] = a;
            }
        }
        float dq = g_dsq[c];
        #pragma unroll
        for (int r = 0; r < 8; ++r) {
            float dv = (fsr[r] + dq) - 2.f * acc[r];
            unsigned long long key =
                ((unsigned long long)__float_as_uint(dv) << 32) | (unsigned)c;
            atomicMin(&best[r], key);
        }
    }
    __syncthreads();
    if (tid < nr)
        g_code_idx[rows[tid]] = (int)(best[tid] & 0xFFFFFFFFu);
}

// ---------------------------------------------------------------------------
// K3: gather quantized rows, write output, accumulate sum((x-q)^2).
// ---------------------------------------------------------------------------
__global__ void gather_loss_kernel(const float* __restrict__ x,
                                   const float* __restrict__ dict,
                                   float* __restrict__ out) {
    __shared__ double bsum[8];
    int warp = threadIdx.x >> 5;
    int lane = threadIdx.x & 31;
    int row  = blockIdx.x * 8 + warp;

    int idx = g_code_idx[row];
    float local = 0.f;
    #pragma unroll
    for (int j = 0; j < 8; ++j) {
        int d = j * 32 + lane;
        float q  = 0.5f * dict[(size_t)d * K + idx];
        float xv = x[(size_t)row * D + d];
        out[(size_t)row * D + d] = q;
        float df = xv - q;
        local = fmaf(df, df, local);
    }
    #pragma unroll
    for (int off = 16; off; off >>= 1)
        local += __shfl_down_sync(0xFFFFFFFFu, local, off);
    if (lane == 0) bsum[warp] = (double)local;
    __syncthreads();
    if (threadIdx.x == 0) {
        double s = 0.0;
        #pragma unroll
        for (int w = 0; w < 8; ++w) s += bsum[w];
        atomicAdd(&g_loss, s);
    }
}

__global__ void finalize_kernel(float* __restrict__ out, int write_loss) {
    if (write_loss && threadIdx.x == 0) {
        out[(size_t)N_ROWS * D] =
            (float)(1.25 * g_loss / (double)((size_t)N_ROWS * D));
    }
}

extern "C" void kernel_launch(void* const* d_in, const int* in_sizes, int n_in,
                              void* d_out, int out_size) {
    const float* x    = (const float*)d_in[0];   // [N_ROWS, D]
    const float* dict = (const float*)d_in[1];   // [D, K]
    float* out = (float*)d_out;

    cudaFuncSetAttribute(prep_x_kernel,
        cudaFuncAttributeMaxDynamicSharedMemorySize, D * XS_STRIDE * 4);
    cudaFuncSetAttribute(mma_argmin_kernel,
        cudaFuncAttributeMaxDynamicSharedMemorySize, SM_TOT);

    prep_dict_kernel<<<(K + 255) / 256, 256>>>(dict);
    prep_x_kernel<<<N_ROWS / 128, 256, D * XS_STRIDE * 4>>>(x);
    mma_argmin_kernel<<<N_ROWS / 128, 256, SM_TOT>>>();
    fallback_kernel<<<N_ROWS / 8, 256>>>(x, dict);
    gather_loss_kernel<<<N_ROWS / 8, 256>>>(x, dict, out);
    finalize_kernel<<<1, 32>>>(out, out_size > N_ROWS * D ? 1 : 0);
}